// round 5
// baseline (speedup 1.0000x reference)
#include <cuda_runtime.h>
#include <math.h>

#define TLEN 8192
#define NTH  1024
#define EPT  8           // elements per thread in prep (NTH*EPT == TLEN)
#define NWARP (NTH/32)   // 32 warps

__device__ float4 g_k4[TLEN / 4];   // final kernel k (with 1/W folded in)

__device__ __forceinline__ float squashf(float v, float lo, float hi) {
    return lo + (hi - lo) / (1.0f + __expf(-v));
}

// Register-hold barrier: forces the 4 float4s (16 floats) to be materialized
// in registers BEFORE anything that reads them through this asm. Chaining all
// loaded data through these forces ptxas to issue every LDG before any FMA.
#define HOLD4(v0, v1, v2, v3)                                              \
    asm volatile("" :                                                      \
        "+f"(v0.x), "+f"(v0.y), "+f"(v0.z), "+f"(v0.w),                    \
        "+f"(v1.x), "+f"(v1.y), "+f"(v1.z), "+f"(v1.w),                    \
        "+f"(v2.x), "+f"(v2.y), "+f"(v2.z), "+f"(v2.w),                    \
        "+f"(v3.x), "+f"(v3.y), "+f"(v3.z), "+f"(v3.w))

// ---------------------------------------------------------------------------
// Prep: compute k_t / W entirely in registers + warp shuffles. (~2us, R4 WIN)
// ---------------------------------------------------------------------------
__global__ void __launch_bounds__(NTH) prep_kernel(
    const float* fsn, const float* fin, const float* fdn, const float* ftn,
    const float* won, const float* wtn, const void* Fin)
{
    __shared__ float sWA[NWARP];
    __shared__ float sWB[NWARP];
    __shared__ float sEx[NTH];

    const int tid  = threadIdx.x;
    const int lane = tid & 31;
    const int wid  = tid >> 5;

    // F is an int scalar (44100); guard against float encoding.
    int   Fi = *(const int*)Fin;
    float Ff = *(const float*)Fin;
    float F  = (Fi > 0 && Fi < 100000000) ? (float)Fi : Ff;

    const float f_start = squashf(*fsn, 200.0f, 4000.0f);
    const float f_inf   = squashf(*fin, 20.0f, 500.0f);
    const float f_decay = squashf(*fdn, 0.0f, 2.0f);
    const float f_T     = squashf(*ftn, 0.0f, 2.0f);
    const float w_off   = squashf(*won, 0.0f, 1.0f);
    const float w_T     = squashf(*wtn, 0.01f, 0.5f);

    const float c      = 0.5098245285339035f * F * 0.3183098861837907f;
    const float lbase  = -0.35667494393873245f - f_decay * 2.302585092994046f;
    const float escale = 0.1f * __expf(f_T * 2.302585092994046f);
    const float inv_wT = 1.0f / w_T;
    const float lk     = lbase * escale * (1.0f / (float)TLEN);

    float atau[EPT + 1];
    float wreg[EPT];
    const int tbase = TLEN - 1 - tid * EPT;   // t(0)
    #pragma unroll
    for (int j = 0; j <= EPT; j++) {
        float ti = (float)(tbase + 1 - j);    // tau(j)
        float f  = f_inf + (f_start - f_inf) * __expf(lk * ti);
        atau[j]  = (f - c) / (f + c);
    }
    float wsum = 0.0f;
    #pragma unroll
    for (int j = 0; j < EPT; j++) {
        float t = (float)(tbase - j) * (1.0f / (float)TLEN);
        wreg[j] = 1.0f / (1.0f + __expf(-(t - w_off) * inv_wT));
        wsum += wreg[j];
    }

    const bool first = (tid == 0);             // owns s=0   (t=8191)
    const bool last  = (tid == NTH - 1);       // owns s=8191 (t=0)

    float lreg[EPT];   // lambda2 after scan1, overwritten by lambda1

    // ===================== scan 1 : lambda2 ==============================
    {
        float A = 1.0f, B = 0.0f;
        #pragma unroll
        for (int j = 0; j < EPT; j++) {
            float Ae = (first && j == 0) ? 0.0f : -atau[j];
            float Be = (last  && j == EPT - 1) ? 0.0f : wreg[j];
            B = fmaf(Ae, B, Be);
            A = Ae * A;
        }
        #pragma unroll
        for (int d = 1; d < 32; d <<= 1) {
            float pA = __shfl_up_sync(0xffffffffu, A, d);
            float pB = __shfl_up_sync(0xffffffffu, B, d);
            if (lane >= d) { B = fmaf(A, pB, B); A = A * pA; }
        }
        if (lane == 31) { sWA[wid] = A; sWB[wid] = B; }
        __syncthreads();
        if (wid == 0) {
            float a = sWA[lane], b = sWB[lane];
            #pragma unroll
            for (int d = 1; d < 32; d <<= 1) {
                float pA = __shfl_up_sync(0xffffffffu, a, d);
                float pB = __shfl_up_sync(0xffffffffu, b, d);
                if (lane >= d) { b = fmaf(a, pB, b); a = a * pA; }
            }
            sWA[lane] = a; sWB[lane] = b;
        }
        __syncthreads();
        float eA = __shfl_up_sync(0xffffffffu, A, 1);
        float eB = __shfl_up_sync(0xffffffffu, B, 1);
        if (lane == 0) { eA = 1.0f; eB = 0.0f; }
        float h = (wid > 0) ? fmaf(eA, sWB[wid - 1], eB) : eB;
        #pragma unroll
        for (int j = 0; j < EPT; j++) {
            float Ae = (first && j == 0) ? 0.0f : -atau[j];
            float Be = (last  && j == EPT - 1) ? 0.0f : wreg[j];
            h = fmaf(Ae, h, Be);
            lreg[j] = h;
        }
    }

    sEx[tid] = lreg[EPT - 1];
    __syncthreads();
    float prevL2 = (tid > 0) ? sEx[tid - 1] : 0.0f;
    __syncthreads();

    // ===================== scan 2 : lambda1 ==============================
    float l2_last = lreg[EPT - 1];
    {
        float A = 1.0f, B = 0.0f;
        #pragma unroll
        for (int j = 0; j < EPT; j++) {
            float bt  = 0.5f * (atau[j + 1] + 1.0f);
            float bt1 = 0.5f * (atau[j] + 1.0f);
            float l2c = lreg[j];
            float l2p = (j == 0) ? prevL2 : lreg[j - 1];
            float Be;
            if (first && j == 0)            Be = bt * l2c;
            else if (last && j == EPT - 1)  Be = bt1 * l2p;
            else                            Be = fmaf(bt, l2c, bt1 * l2p);
            float Ae = (first && j == 0) ? 0.0f : -atau[j];
            B = fmaf(Ae, B, Be);
            A = Ae * A;
        }
        #pragma unroll
        for (int d = 1; d < 32; d <<= 1) {
            float pA = __shfl_up_sync(0xffffffffu, A, d);
            float pB = __shfl_up_sync(0xffffffffu, B, d);
            if (lane >= d) { B = fmaf(A, pB, B); A = A * pA; }
        }
        if (lane == 31) { sWA[wid] = A; sWB[wid] = B; }
        __syncthreads();
        if (wid == 0) {
            float a = sWA[lane], b = sWB[lane];
            #pragma unroll
            for (int d = 1; d < 32; d <<= 1) {
                float pA = __shfl_up_sync(0xffffffffu, a, d);
                float pB = __shfl_up_sync(0xffffffffu, b, d);
                if (lane >= d) { b = fmaf(a, pB, b); a = a * pA; }
            }
            sWA[lane] = a; sWB[lane] = b;
        }
        __syncthreads();
        float eA = __shfl_up_sync(0xffffffffu, A, 1);
        float eB = __shfl_up_sync(0xffffffffu, B, 1);
        if (lane == 0) { eA = 1.0f; eB = 0.0f; }
        float h = (wid > 0) ? fmaf(eA, sWB[wid - 1], eB) : eB;
        float l2p = prevL2;
        #pragma unroll
        for (int j = 0; j < EPT; j++) {
            float bt  = 0.5f * (atau[j + 1] + 1.0f);
            float bt1 = 0.5f * (atau[j] + 1.0f);
            float l2c = lreg[j];
            float Be;
            if (first && j == 0)            Be = bt * l2c;
            else if (last && j == EPT - 1)  Be = bt1 * l2p;
            else                            Be = fmaf(bt, l2c, bt1 * l2p);
            float Ae = (first && j == 0) ? 0.0f : -atau[j];
            h = fmaf(Ae, h, Be);
            lreg[j] = h;                    // l1
            l2p = l2c;
        }
    }

    __syncthreads();
    sEx[tid] = lreg[EPT - 1];
    __syncthreads();
    float prevL1 = (tid > 0) ? sEx[tid - 1] : 0.0f;

    // ===================== W = sum(w) ====================================
    #pragma unroll
    for (int d = 16; d > 0; d >>= 1)
        wsum += __shfl_down_sync(0xffffffffu, wsum, d);
    __syncthreads();
    if (lane == 0) sWA[wid] = wsum;
    __syncthreads();
    if (tid == 0) {
        float s = 0.0f;
        #pragma unroll
        for (int i = 0; i < NWARP; i++) s += sWA[i];
        sWB[0] = 1.0f / s;
    }
    __syncthreads();
    const float invW = sWB[0];

    // ===================== emit k ========================================
    float* kf = (float*)g_k4;
    #pragma unroll
    for (int j = 0; j < EPT; j++) {
        float bt  = 0.5f * (atau[j + 1] + 1.0f);
        float bt1 = 0.5f * (atau[j] + 1.0f);
        float l1c = lreg[j];
        float l1p = (j == 0) ? prevL1 : lreg[j - 1];
        float kv;
        if (first && j == 0) {
            kv = bt * l1c;
        } else if (last && j == EPT - 1) {
            kv = wreg[EPT - 1] + fmaf(bt1, lreg[EPT - 2], l1c + l2_last);
        } else {
            kv = fmaf(bt, l1c, bt1 * l1p);
        }
        kf[tbase - j] = kv * invW;
    }
}

// ---------------------------------------------------------------------------
// GEMV: 1 row per CTA, 256 threads. All 8 x-float4 + 8 k-float4 loads are
// forced to issue BEFORE any FMA via register-hold asm -> per-warp MLP = 16
// LDG.128 (64 cache lines) in flight.
// ---------------------------------------------------------------------------
__global__ void __launch_bounds__(256) gemv_kernel(
    const float* __restrict__ X, float* __restrict__ out)
{
    const int row = blockIdx.x;
    const float4* __restrict__ xr = (const float4*)(X + (size_t)row * TLEN);

    float4 x0 = __ldcs(&xr[0 * 256 + threadIdx.x]);
    float4 x1 = __ldcs(&xr[1 * 256 + threadIdx.x]);
    float4 x2 = __ldcs(&xr[2 * 256 + threadIdx.x]);
    float4 x3 = __ldcs(&xr[3 * 256 + threadIdx.x]);
    float4 x4 = __ldcs(&xr[4 * 256 + threadIdx.x]);
    float4 x5 = __ldcs(&xr[5 * 256 + threadIdx.x]);
    float4 x6 = __ldcs(&xr[6 * 256 + threadIdx.x]);
    float4 x7 = __ldcs(&xr[7 * 256 + threadIdx.x]);
    float4 k0 = g_k4[0 * 256 + threadIdx.x];
    float4 k1 = g_k4[1 * 256 + threadIdx.x];
    float4 k2 = g_k4[2 * 256 + threadIdx.x];
    float4 k3 = g_k4[3 * 256 + threadIdx.x];
    float4 k4 = g_k4[4 * 256 + threadIdx.x];
    float4 k5 = g_k4[5 * 256 + threadIdx.x];
    float4 k6 = g_k4[6 * 256 + threadIdx.x];
    float4 k7 = g_k4[7 * 256 + threadIdx.x];

    // Force all 16 LDG.128s to issue before any consumer.
    HOLD4(x0, x1, x2, x3);
    HOLD4(x4, x5, x6, x7);
    HOLD4(k0, k1, k2, k3);
    HOLD4(k4, k5, k6, k7);

    float a0, a1, a2, a3;
    a0 = x0.x * k0.x;            a1 = x0.y * k0.y;
    a2 = x0.z * k0.z;            a3 = x0.w * k0.w;
    a0 = fmaf(x1.x, k1.x, a0);   a1 = fmaf(x1.y, k1.y, a1);
    a2 = fmaf(x1.z, k1.z, a2);   a3 = fmaf(x1.w, k1.w, a3);
    a0 = fmaf(x2.x, k2.x, a0);   a1 = fmaf(x2.y, k2.y, a1);
    a2 = fmaf(x2.z, k2.z, a2);   a3 = fmaf(x2.w, k2.w, a3);
    a0 = fmaf(x3.x, k3.x, a0);   a1 = fmaf(x3.y, k3.y, a1);
    a2 = fmaf(x3.z, k3.z, a2);   a3 = fmaf(x3.w, k3.w, a3);
    a0 = fmaf(x4.x, k4.x, a0);   a1 = fmaf(x4.y, k4.y, a1);
    a2 = fmaf(x4.z, k4.z, a2);   a3 = fmaf(x4.w, k4.w, a3);
    a0 = fmaf(x5.x, k5.x, a0);   a1 = fmaf(x5.y, k5.y, a1);
    a2 = fmaf(x5.z, k5.z, a2);   a3 = fmaf(x5.w, k5.w, a3);
    a0 = fmaf(x6.x, k6.x, a0);   a1 = fmaf(x6.y, k6.y, a1);
    a2 = fmaf(x6.z, k6.z, a2);   a3 = fmaf(x6.w, k6.w, a3);
    a0 = fmaf(x7.x, k7.x, a0);   a1 = fmaf(x7.y, k7.y, a1);
    a2 = fmaf(x7.z, k7.z, a2);   a3 = fmaf(x7.w, k7.w, a3);

    float acc = (a0 + a1) + (a2 + a3);

    // warp reduce
    #pragma unroll
    for (int off = 16; off > 0; off >>= 1)
        acc += __shfl_down_sync(0xffffffffu, acc, off);

    __shared__ float sred[8];
    int w = threadIdx.x >> 5, l = threadIdx.x & 31;
    if (l == 0) sred[w] = acc;
    __syncthreads();
    if (threadIdx.x == 0) {
        float s = 0.0f;
        #pragma unroll
        for (int i = 0; i < 8; i++) s += sred[i];
        out[row] = s;
    }
}

extern "C" void kernel_launch(void* const* d_in, const int* in_sizes, int n_in,
                              void* d_out, int out_size)
{
    const float* X = (const float*)d_in[0];
    const void*  F = d_in[1];

    prep_kernel<<<1, NTH>>>(
        (const float*)d_in[2], (const float*)d_in[3], (const float*)d_in[4],
        (const float*)d_in[5], (const float*)d_in[6], (const float*)d_in[7], F);

    int rows = in_sizes[0] / TLEN;
    gemv_kernel<<<rows, 256>>>(X, (float*)d_out);
}